// round 16
// baseline (speedup 1.0000x reference)
#include <cuda_runtime.h>
#include <cuda_bf16.h>
#include <cstdint>
#include <cstddef>

// ---------------------------------------------------------------------------
// Problem constants
// ---------------------------------------------------------------------------
#define NA   50000
#define NP   100000
#define NE   800000
#define NEL  100000
#define CD   256

typedef __nv_bfloat16 bf;

// ---------------------------------------------------------------------------
// Device scratch
// ---------------------------------------------------------------------------
__device__ bf g_xaH[2][(size_t)NA * CD];
__device__ bf g_xaL[2][(size_t)NA * CD];
__device__ bf g_xpH[2][(size_t)NP * CD];
__device__ bf g_xpL[2][(size_t)NP * CD];
__device__ float g_xaF[2][(size_t)NA * CD];   // fp32 activation copies (agg input)
__device__ float g_xpF[2][(size_t)NP * CD];
__device__ bf g_aWH[(size_t)NP * CD];
__device__ bf g_aWL[(size_t)NP * CD];
__device__ bf g_aCH[(size_t)NP * CD];
__device__ bf g_aCL[(size_t)NP * CD];
__device__ bf g_aAH[(size_t)NA * CD];
__device__ bf g_aAL[(size_t)NA * CD];
__device__ bf g_xinAH[(size_t)NA * 128];
__device__ bf g_xinAL[(size_t)NA * 128];
__device__ bf g_xinPH[(size_t)NP * 128];
__device__ bf g_xinPL[(size_t)NP * 128];
// Per-layer prepped weight planes
__device__ bf g_BP1h[256 * 384];
__device__ bf g_BP1l[256 * 384];
__device__ bf g_BA1h[256 * 256];
__device__ bf g_BA1l[256 * 256];
__device__ bf g_BPh3[3][256 * 768];
__device__ bf g_BPl3[3][256 * 768];
__device__ bf g_BAh3[3][256 * 512];
__device__ bf g_BAl3[3][256 * 512];
__device__ bf g_BDh[512 * 256];
__device__ bf g_BDl[512 * 256];
__device__ float g_bc[4][256];
__device__ float g_TB[(size_t)NA * 512];
// CSR
__device__ int g_rpW[NP + 1];
__device__ int g_rpC[NP + 1];
__device__ int g_rpA[NA + 1];
__device__ int g_colW[NE];
__device__ int g_colC[NE];
__device__ int g_colA[NE];
__device__ int g_cnt[2 * NP + NA];   // [W | C | A]
__device__ int g_sync;               // scan-done flag (0 at launch entry/exit)
__device__ int g_fin;                // fill-done counter (0 at launch entry/exit)

// ---------------------------------------------------------------------------
// Baseline-PTX helpers (sm_80+: mma.sync bf16, ldmatrix, cp.async; sm_100: f32x2)
// ---------------------------------------------------------------------------
__device__ __forceinline__ uint32_t smem_u32(const void* p) {
    uint32_t a;
    asm("{ .reg .u64 t; cvta.to.shared.u64 t, %1; cvt.u32.u64 %0, t; }"
        : "=r"(a) : "l"(p));
    return a;
}
__device__ __forceinline__ void cpasync16(uint32_t dst, const void* src, int sz) {
    asm volatile("cp.async.cg.shared.global [%0], [%1], 16, %2;"
                 :: "r"(dst), "l"(src), "r"(sz) : "memory");
}
#define CP_COMMIT() asm volatile("cp.async.commit_group;" ::: "memory")
#define CP_WAIT0()  asm volatile("cp.async.wait_group 0;" ::: "memory")

__device__ __forceinline__ void ldsm4(uint32_t* r, uint32_t addr) {
    asm volatile("ldmatrix.sync.aligned.m8n8.x4.shared.b16 {%0,%1,%2,%3}, [%4];"
                 : "=r"(r[0]), "=r"(r[1]), "=r"(r[2]), "=r"(r[3]) : "r"(addr));
}
__device__ __forceinline__ void mma16816(float* c, const uint32_t* a, const uint32_t* b) {
    asm volatile(
        "mma.sync.aligned.m16n8k16.row.col.f32.bf16.bf16.f32 "
        "{%0,%1,%2,%3}, {%4,%5,%6,%7}, {%8,%9}, {%0,%1,%2,%3};"
        : "+f"(c[0]), "+f"(c[1]), "+f"(c[2]), "+f"(c[3])
        : "r"(a[0]), "r"(a[1]), "r"(a[2]), "r"(a[3]), "r"(b[0]), "r"(b[1]));
}
// Packed fp32x2 add (PTX ISA sm_100+, NOT sm_100a-gated)
__device__ __forceinline__ unsigned long long addf32x2(unsigned long long a,
                                                       unsigned long long b) {
    unsigned long long c;
    asm("add.rn.f32x2 %0, %1, %2;" : "=l"(c) : "l"(a), "l"(b));
    return c;
}

// ---------------------------------------------------------------------------
// Split-precision helpers
// ---------------------------------------------------------------------------
__device__ __forceinline__ void split1(float v, bf& h, bf& l) {
    h = __float2bfloat16(v);
    l = __float2bfloat16(v - __bfloat162float(h));
}
__device__ __forceinline__ uint32_t packbf2(bf a, bf b) {
    __nv_bfloat162 p = __halves2bfloat162(a, b);
    return *reinterpret_cast<uint32_t*>(&p);
}

// ---------------------------------------------------------------------------
// Front kernel 1: histogram + ALL weight/bias prep (block-range dispatch)
// ---------------------------------------------------------------------------
__device__ void hist_body(const int* __restrict__ wdst, const int* __restrict__ cdst,
                          const int* __restrict__ wsrc, int rb, int nb) {
    int* cW = g_cnt;
    int* cC = g_cnt + NP;
    int* cA = g_cnt + 2 * NP;
    for (int e = rb * blockDim.x + threadIdx.x; e < NE; e += nb * blockDim.x) {
        atomicAdd(&cW[wdst[e]], 1);
        atomicAdd(&cC[cdst[e]], 1);
        atomicAdd(&cA[wsrc[e]], 1);
    }
}

__device__ __forceinline__ void prep_emit(int j, int Ktot, int Kseg,
                                          const float* W0, const float* W1s,
                                          const float* W2a, const float* W2b,
                                          bf* Bh, bf* Bl) {
    int n = j / Ktot, kg = j - n * Ktot;
    int seg = kg / Kseg, k = kg - seg * Kseg;
    float v;
    if (seg == 0)      v = W0[k * 256 + n];
    else if (seg == 1) v = W1s[k * 256 + n];
    else               v = W2a[k * 256 + n] + W2b[k * 256 + n];
    bf h, l;
    split1(v, h, l);
    Bh[j] = h;
    Bl[j] = l;
}

#define P1_SZ  98304     // 256*384
#define PL_SZ  196608    // 256*768
#define A1_SZ  65536     // 256*256
#define AL_SZ  131072    // 256*512
#define DEC_SZ 131072    // 512*256
#define PREP_TOT (P1_SZ + 3 * PL_SZ + A1_SZ + 3 * AL_SZ + DEC_SZ + 1024)

__device__ void prep_body(const float* Wl1, const float* bl1, const float* Wr1,
                          const float* Wl, const float* bl, const float* Wr,
                          const float* dW1, int rb, int nb) {
    for (int i = rb * blockDim.x + threadIdx.x; i < PREP_TOT; i += nb * blockDim.x) {
        int r = i;
        if (r < P1_SZ) {
            prep_emit(r, 384, 128, Wl1, Wl1 + 2 * 32768, Wr1, Wr1 + 2 * 32768,
                      g_BP1h, g_BP1l);
            continue;
        }
        r -= P1_SZ;
        if (r < 3 * PL_SZ) {
            int l = r / PL_SZ, j = r - l * PL_SZ;
            const float* Wl_l = Wl + (size_t)l * 3 * 65536;
            const float* Wr_l = Wr + (size_t)l * 3 * 65536;
            prep_emit(j, 768, 256, Wl_l, Wl_l + 2 * 65536, Wr_l, Wr_l + 2 * 65536,
                      g_BPh3[l], g_BPl3[l]);
            continue;
        }
        r -= 3 * PL_SZ;
        if (r < A1_SZ) {
            prep_emit(r, 256, 128, Wl1 + 32768, Wr1 + 32768, nullptr, nullptr,
                      g_BA1h, g_BA1l);
            continue;
        }
        r -= A1_SZ;
        if (r < 3 * AL_SZ) {
            int l = r / AL_SZ, j = r - l * AL_SZ;
            const float* Wl_l = Wl + (size_t)l * 3 * 65536;
            const float* Wr_l = Wr + (size_t)l * 3 * 65536;
            prep_emit(j, 512, 256, Wl_l + 65536, Wr_l + 65536, nullptr, nullptr,
                      g_BAh3[l], g_BAl3[l]);
            continue;
        }
        r -= 3 * AL_SZ;
        if (r < DEC_SZ) {
            int n = r >> 8, k = r & 255;
            float v = (n < 256) ? dW1[k * 256 + n] : dW1[(256 + k) * 256 + (n - 256)];
            bf h, l;
            split1(v, h, l);
            g_BDh[r] = h;
            g_BDl[r] = l;
            continue;
        }
        r -= DEC_SZ;
        if (r < 256) {
            g_bc[0][r] = bl1[r] + bl1[512 + r];
        } else if (r < 1024) {
            int l = (r - 256) >> 8, c = r & 255;
            g_bc[l + 1][c] = bl[l * 768 + c] + bl[l * 768 + 512 + c];
        }
    }
}

#define HIST_B 1024
#define PREP_B 512
__global__ void k_front1(const int* __restrict__ wdst, const int* __restrict__ cdst,
                         const int* __restrict__ wsrc,
                         const float* __restrict__ Wl1, const float* __restrict__ bl1,
                         const float* __restrict__ Wr1,
                         const float* __restrict__ Wl, const float* __restrict__ bl,
                         const float* __restrict__ Wr, const float* __restrict__ dW1) {
    int b = blockIdx.x;
    if (b < HIST_B) hist_body(wdst, cdst, wsrc, b, HIST_B);
    else            prep_body(Wl1, bl1, Wr1, Wl, bl, Wr, dW1, b - HIST_B, PREP_B);
}

// ---------------------------------------------------------------------------
// Front kernel 2: scan (blocks 0-2) + input split + CSR fill (spin-waits on
// scan completion via threadfence/flag). 1024 thr/block.
// ---------------------------------------------------------------------------
__device__ void scan_body(int* __restrict__ cnt, int* __restrict__ rp, int n) {
    __shared__ int wsum[32];
    __shared__ int carry;
    int t = threadIdx.x, lane = t & 31, wid = t >> 5;
    if (t == 0) carry = 0;
    __syncthreads();
    const int TILE = 1024 * 16;
    for (int base = 0; base < n; base += TILE) {
        int idx0 = base + t * 16;
        int v[16];
        int tot = 0;
        if (idx0 < n) {
            int4* p = (int4*)(cnt + idx0);
            int4 a0 = p[0], a1 = p[1], a2 = p[2], a3 = p[3];
            v[0] = a0.x;  v[1] = a0.y;  v[2] = a0.z;  v[3] = a0.w;
            v[4] = a1.x;  v[5] = a1.y;  v[6] = a1.z;  v[7] = a1.w;
            v[8] = a2.x;  v[9] = a2.y;  v[10] = a2.z; v[11] = a2.w;
            v[12] = a3.x; v[13] = a3.y; v[14] = a3.z; v[15] = a3.w;
            #pragma unroll
            for (int j = 0; j < 16; j++) tot += v[j];
            int4 z = make_int4(0, 0, 0, 0);
            p[0] = z; p[1] = z; p[2] = z; p[3] = z;
        } else {
            #pragma unroll
            for (int j = 0; j < 16; j++) v[j] = 0;
        }
        int x = tot;
        #pragma unroll
        for (int off = 1; off < 32; off <<= 1) {
            int y = __shfl_up_sync(0xffffffffu, x, off);
            if (lane >= off) x += y;
        }
        if (lane == 31) wsum[wid] = x;
        __syncthreads();
        if (wid == 0) {
            int s = wsum[lane];
            #pragma unroll
            for (int off = 1; off < 32; off <<= 1) {
                int y = __shfl_up_sync(0xffffffffu, s, off);
                if (lane >= off) s += y;
            }
            wsum[lane] = s;
        }
        __syncthreads();
        if (idx0 < n) {
            int run = ((wid > 0) ? wsum[wid - 1] : 0) + carry + x - tot;  // exclusive
            int o[16];
            #pragma unroll
            for (int j = 0; j < 16; j++) { o[j] = run; run += v[j]; }
            int4* q = (int4*)(rp + idx0);
            q[0] = make_int4(o[0], o[1], o[2], o[3]);
            q[1] = make_int4(o[4], o[5], o[6], o[7]);
            q[2] = make_int4(o[8], o[9], o[10], o[11]);
            q[3] = make_int4(o[12], o[13], o[14], o[15]);
        }
        __syncthreads();
        if (t == 0) carry += wsum[31];
        __syncthreads();
    }
    if (t == 0) rp[n] = carry;
}

__device__ void split_body(const float* __restrict__ xa, const float* __restrict__ xp,
                           int rb, int nb) {
    const int n1 = NA * 128, n2 = NP * 128;
    for (int i = rb * blockDim.x + threadIdx.x; i < n1 + n2; i += nb * blockDim.x) {
        bf h, l;
        if (i < n1) {
            split1(xa[i], h, l);
            g_xinAH[i] = h; g_xinAL[i] = l;
        } else {
            int j = i - n1;
            split1(xp[j], h, l);
            g_xinPH[j] = h; g_xinPL[j] = l;
        }
    }
}

__device__ void fill_body(const int* __restrict__ key, const int* __restrict__ val,
                          const int* __restrict__ rp, int* __restrict__ cur,
                          int* __restrict__ col, int rb, int nb) {
    for (int e = rb * blockDim.x + threadIdx.x; e < NE; e += nb * blockDim.x) {
        int k = key[e];
        int pos = rp[k] + atomicAdd(&cur[k], 1);
        col[pos] = val[e];
    }
}

#define SPLIT_B 512
#define FILLB2  128
#define NFILL2  (3 * FILLB2)

__global__ void k_front2(const float* __restrict__ xa, const float* __restrict__ xp,
                         const int* __restrict__ wdst, const int* __restrict__ wsrc,
                         const int* __restrict__ cdst, const int* __restrict__ csrc) {
    int b = blockIdx.x;
    if (b < 3) {
        if (b == 0)      scan_body(g_cnt,          g_rpW, NP);
        else if (b == 1) scan_body(g_cnt + NP,     g_rpC, NP);
        else             scan_body(g_cnt + 2 * NP, g_rpA, NA);
        __syncthreads();
        __threadfence();
        if (threadIdx.x == 0) atomicAdd(&g_sync, 1);
        return;
    }
    b -= 3;
    if (b < SPLIT_B) { split_body(xa, xp, b, SPLIT_B); return; }
    b -= SPLIT_B;
    // CSR fill: wait until all 3 scans are published.
    if (threadIdx.x == 0) {
        while (atomicAdd(&g_sync, 0) < 3) __nanosleep(64);
    }
    __syncthreads();
    int job = b / FILLB2, rb = b % FILLB2;
    if (job == 0)      fill_body(wdst, wsrc, g_rpW, g_cnt,          g_colW, rb, FILLB2);
    else if (job == 1) fill_body(cdst, csrc, g_rpC, g_cnt + NP,     g_colC, rb, FILLB2);
    else               fill_body(wsrc, wdst, g_rpA, g_cnt + 2 * NP, g_colA, rb, FILLB2);
    __syncthreads();
    if (threadIdx.x == 0) {
        int f = atomicAdd(&g_fin, 1);
        if (f == NFILL2 - 1) { g_sync = 0; g_fin = 0; }   // reset for next replay
    }
}

// ---------------------------------------------------------------------------
// Merged mean aggregation: 3 jobs, fp32 gather input, f32x2 SIMD accumulate,
// 2-edge unrolled dual accumulator chains (ILP for latency hiding).
// ---------------------------------------------------------------------------
struct AggJob {
    const float* xf;
    const int *rp, *col;
    bf *oh, *ol;
    int ndst;
};

template <int DIM>
__device__ void agg_body(const AggJob& J, int rb, int nb) {
    constexpr int EPL = DIM / 32;   // 4 or 8 floats per lane
    constexpr int W = EPL / 2;      // 2 or 4 f32x2 words
    int lane = threadIdx.x & 31;
    int w  = rb * (blockDim.x >> 5) + (threadIdx.x >> 5);
    int nw = nb * (blockDim.x >> 5);
    const float* x0 = J.xf + lane * EPL;
    const int* __restrict__ col = J.col;
    for (int d = w; d < J.ndst; d += nw) {
        int e0 = J.rp[d], e1 = J.rp[d + 1];
        unsigned long long a0[W], a1[W];
        #pragma unroll
        for (int j = 0; j < W; j++) { a0[j] = 0ull; a1[j] = 0ull; }
        int e = e0;
        for (; e + 1 < e1; e += 2) {
            int off0 = col[e] * DIM;
            int off1 = col[e + 1] * DIM;
            unsigned long long v0[W], v1[W];
            if (W == 4) {
                *(ulonglong4*)v0 = *(const ulonglong4*)(x0 + off0);
                *(ulonglong4*)v1 = *(const ulonglong4*)(x0 + off1);
            } else {
                *(ulonglong2*)v0 = *(const ulonglong2*)(x0 + off0);
                *(ulonglong2*)v1 = *(const ulonglong2*)(x0 + off1);
            }
            #pragma unroll
            for (int j = 0; j < W; j++) {
                a0[j] = addf32x2(a0[j], v0[j]);
                a1[j] = addf32x2(a1[j], v1[j]);
            }
        }
        if (e < e1) {
            int off0 = col[e] * DIM;
            unsigned long long v0[W];
            if (W == 4) *(ulonglong4*)v0 = *(const ulonglong4*)(x0 + off0);
            else        *(ulonglong2*)v0 = *(const ulonglong2*)(x0 + off0);
            #pragma unroll
            for (int j = 0; j < W; j++) a0[j] = addf32x2(a0[j], v0[j]);
        }
        #pragma unroll
        for (int j = 0; j < W; j++) a0[j] = addf32x2(a0[j], a1[j]);
        float inv = 1.0f / (float)max(e1 - e0, 1);
        uint32_t ohw[W], olw[W];
        #pragma unroll
        for (int j = 0; j < W; j++) {
            float v0 = __uint_as_float((uint32_t)a0[j]) * inv;
            float v1 = __uint_as_float((uint32_t)(a0[j] >> 32)) * inv;
            bf h0, l0, h1, l1;
            split1(v0, h0, l0);
            split1(v1, h1, l1);
            ohw[j] = packbf2(h0, h1);
            olw[j] = packbf2(l0, l1);
        }
        size_t obase = (size_t)d * DIM + lane * EPL;
        if (W == 4) {
            *(uint4*)(J.oh + obase) = *(uint4*)ohw;
            *(uint4*)(J.ol + obase) = *(uint4*)olw;
        } else {
            *(uint2*)(J.oh + obase) = *(uint2*)ohw;
            *(uint2*)(J.ol + obase) = *(uint2*)olw;
        }
    }
}

template <int DIM>
__global__ void k_agg3(AggJob j0, AggJob j1, AggJob j2, int nb0, int nb1, int nb2) {
    int b = blockIdx.x;
    if (b < nb0)            agg_body<DIM>(j0, b, nb0);
    else if (b < nb0 + nb1) agg_body<DIM>(j1, b - nb0, nb1);
    else                    agg_body<DIM>(j2, b - nb0 - nb1, nb2);
}

// ---------------------------------------------------------------------------
// Split-bf16 tensor-core GEMM (mma.sync m16n8k16, cp.async double buffer)
// Block tile 128x64 (was 128x128): smem/stage 30.75KB -> 3 CTAs/SM for
// latency hiding (occ 24% -> ~37%). Warp tile 32x32 (acc 32 regs).
// Single-barrier pipeline: wait0 -> sync -> issue load(s+1) -> compute(s).
// ---------------------------------------------------------------------------
#define ROWB   80
#define OFF_AH 0
#define OFF_AL 10240
#define OFF_BH 20480
#define OFF_BL 25600
#define STAGE  30720
#define SMEM_TOTAL (2 * STAGE)

struct GemmP {
    int M, Ktot, Kseg, Nall, relu;
    const bf *A0h, *A0l, *A1h, *A1l, *A2h, *A2l, *Bh, *Bl;
    const float* bias;
    float* Cf;
    bf *Ch, *Cl;
    float* Cx;
};

__device__ __forceinline__ void stage_load(const GemmP& P, uint32_t sb, int stg,
                                           int tid, int bm, int n_off, int s) {
    int kg = s * 32;
    int seg = kg / P.Kseg;
    int kof = kg - seg * P.Kseg;
    const bf* ah = (seg == 0) ? P.A0h : (seg == 1) ? P.A1h : P.A2h;
    const bf* al = (seg == 0) ? P.A0l : (seg == 1) ? P.A1l : P.A2l;
    uint32_t base = sb + stg * STAGE;
    // 1536 cp.async of 16B: A hi 512, A lo 512, B hi 256, B lo 256
    #pragma unroll
    for (int i = 0; i < 6; i++) {
        int c = tid + 256 * i;
        if (c < 1024) {
            int plane = c >> 9;
            int cc = c & 511;
            int row = cc >> 2, kc = cc & 3;
            uint32_t d = base + (plane ? OFF_AL : OFF_AH) + row * ROWB + kc * 16;
            const bf* src = plane ? al : ah;
            int gr = bm + row;
            int sz = (gr < P.M) ? 16 : 0;
            int grc = (gr < P.M) ? gr : (P.M - 1);
            cpasync16(d, src + (size_t)grc * P.Kseg + kof + kc * 8, sz);
        } else {
            int cc = c - 1024;
            int plane = cc >> 8;
            int c2 = cc & 255;
            int row = c2 >> 2, kc = c2 & 3;
            uint32_t d = base + (plane ? OFF_BL : OFF_BH) + row * ROWB + kc * 16;
            const bf* src = plane ? P.Bl : P.Bh;
            cpasync16(d, src + (size_t)(n_off + row) * P.Ktot + kg + kc * 8, 16);
        }
    }
}

__global__ void __launch_bounds__(256, 3)
k_mgemm2(GemmP p, GemmP q, int yP) {
    extern __shared__ char smem[];
    uint32_t sb = smem_u32(smem);
    int tid = threadIdx.x;
    int lane = tid & 31;
    int warp = tid >> 5;
    int wm = warp >> 1;      // 0..3 (M, 32 rows each)
    int wn = warp & 1;       // 0..1 (N, 32 cols each)

    GemmP P;
    int by = blockIdx.y;
    if (by < yP) P = p;
    else { P = q; by -= yP; }
    int bm = by * 128;
    int n_off = blockIdx.x * 64;
    int S = P.Ktot / 32;

    float acc[2][4][4];
    #pragma unroll
    for (int a = 0; a < 2; a++)
        #pragma unroll
        for (int b = 0; b < 4; b++)
            #pragma unroll
            for (int c = 0; c < 4; c++) acc[a][b][c] = 0.f;

    uint32_t lmo = (uint32_t)((lane & 15) * ROWB + (lane >> 4) * 16);

    stage_load(P, sb, 0, tid, bm, n_off, 0);
    CP_COMMIT();

    for (int s = 0; s < S; s++) {
        CP_WAIT0();            // stage s landed (single group in flight)
        __syncthreads();       // all warps done with compute(s-1) AND see stage s
        if (s + 1 < S) {
            stage_load(P, sb, (s + 1) & 1, tid, bm, n_off, s + 1);
            CP_COMMIT();       // overlaps with compute(s) below
        }

        uint32_t base = sb + (s & 1) * STAGE;
        #pragma unroll
        for (int ks = 0; ks < 2; ks++) {
            uint32_t kb = ks * 32;
            uint32_t af[2][4], bhf[4][2], blf[4][2];
            #pragma unroll
            for (int mt = 0; mt < 2; mt++)
                ldsm4(af[mt], base + OFF_AH + (wm * 32 + mt * 16) * ROWB + kb + lmo);
            #pragma unroll
            for (int bt = 0; bt < 2; bt++) {
                uint32_t r[4];
                ldsm4(r, base + OFF_BH + (wn * 32 + bt * 16) * ROWB + kb + lmo);
                bhf[2 * bt][0] = r[0]; bhf[2 * bt][1] = r[2];
                bhf[2 * bt + 1][0] = r[1]; bhf[2 * bt + 1][1] = r[3];
            }
            #pragma unroll
            for (int bt = 0; bt < 2; bt++) {
                uint32_t r[4];
                ldsm4(r, base + OFF_BL + (wn * 32 + bt * 16) * ROWB + kb + lmo);
                blf[2 * bt][0] = r[0]; blf[2 * bt][1] = r[2];
                blf[2 * bt + 1][0] = r[1]; blf[2 * bt + 1][1] = r[3];
            }
            #pragma unroll
            for (int mt = 0; mt < 2; mt++)
                #pragma unroll
                for (int nt = 0; nt < 4; nt++) mma16816(acc[mt][nt], af[mt], bhf[nt]);
            #pragma unroll
            for (int mt = 0; mt < 2; mt++)
                #pragma unroll
                for (int nt = 0; nt < 4; nt++) mma16816(acc[mt][nt], af[mt], blf[nt]);
            #pragma unroll
            for (int mt = 0; mt < 2; mt++)
                ldsm4(af[mt], base + OFF_AL + (wm * 32 + mt * 16) * ROWB + kb + lmo);
            #pragma unroll
            for (int mt = 0; mt < 2; mt++)
                #pragma unroll
                for (int nt = 0; nt < 4; nt++) mma16816(acc[mt][nt], af[mt], bhf[nt]);
        }
        // no trailing barrier: next iteration's sync (after wait0) protects reuse
    }

    // Epilogue
    #pragma unroll
    for (int mt = 0; mt < 2; mt++) {
        int r0 = bm + wm * 32 + mt * 16 + (lane >> 2);
        #pragma unroll
        for (int half = 0; half < 2; half++) {
            int row = r0 + half * 8;
            if (row >= P.M) continue;
            #pragma unroll
            for (int nt = 0; nt < 4; nt++) {
                int gcol = n_off + wn * 32 + nt * 8 + (lane & 3) * 2;
                float v0 = acc[mt][nt][half * 2 + 0];
                float v1 = acc[mt][nt][half * 2 + 1];
                if (P.Cf) {
                    *(float2*)(P.Cf + (size_t)row * P.Nall + gcol) = make_float2(v0, v1);
                } else {
                    v0 += P.bias[gcol];
                    v1 += P.bias[gcol + 1];
                    if (P.relu) { v0 = fmaxf(v0, 0.f); v1 = fmaxf(v1, 0.f); }
                    if (P.Cx)
                        *(float2*)(P.Cx + (size_t)row * P.Nall + gcol) = make_float2(v0, v1);
                    bf h0, l0, h1, l1;
                    split1(v0, h0, l0);
                    split1(v1, h1, l1);
                    *(uint32_t*)(P.Ch + (size_t)row * P.Nall + gcol) = packbf2(h0, h1);
                    *(uint32_t*)(P.Cl + (size_t)row * P.Nall + gcol) = packbf2(l0, l1);
                }
            }
        }
    }
}

// ---------------------------------------------------------------------------
// Fused edge decoder
// ---------------------------------------------------------------------------
__global__ void k_edge(const int* __restrict__ src, const int* __restrict__ dst,
                       const float* __restrict__ TB, const float* __restrict__ b1,
                       const float* __restrict__ W2, const float* __restrict__ b2,
                       float* __restrict__ out) {
    int lane = threadIdx.x & 31;
    int w  = (blockIdx.x * blockDim.x + threadIdx.x) >> 5;
    int nw = (gridDim.x * blockDim.x) >> 5;
    for (int e = w; e < NEL; e += nw) {
        int s = src[e], d = dst[e];
        const float* Ts = TB + (size_t)s * 512;
        const float* Td = TB + (size_t)d * 512 + 256;
        float sum = 0.f;
        #pragma unroll
        for (int k = 0; k < 8; k++) {
            int c = lane + 32 * k;
            float h = Ts[c] + Td[c] + b1[c];
            h = fmaxf(h, 0.f);
            sum += h * W2[c];
        }
        #pragma unroll
        for (int off = 16; off; off >>= 1)
            sum += __shfl_down_sync(0xffffffffu, sum, off);
        if (lane == 0) out[e] = sum + b2[0];
    }
}

// ---------------------------------------------------------------------------
// Host
// ---------------------------------------------------------------------------
template <typename T>
static T* sym_addr(const void* sym) {
    void* p = nullptr;
    cudaGetSymbolAddress(&p, sym);
    return (T*)p;
}

extern "C" void kernel_launch(void* const* d_in, const int* in_sizes, int n_in,
                              void* d_out, int out_size) {
    const float* x_author = (const float*)d_in[0];
    const float* x_paper  = (const float*)d_in[1];
    const float* Wl1      = (const float*)d_in[2];
    const float* bl1      = (const float*)d_in[3];
    const float* Wr1      = (const float*)d_in[4];
    const float* Wl       = (const float*)d_in[5];
    const float* bl       = (const float*)d_in[6];
    const float* Wr       = (const float*)d_in[7];
    const float* dec_W1   = (const float*)d_in[8];
    const float* dec_b1   = (const float*)d_in[9];
    const float* dec_W2   = (const float*)d_in[10];
    const float* dec_b2   = (const float*)d_in[11];
    const int* wsrc = (const int*)d_in[12];
    const int* wdst = (const int*)d_in[13];
    const int* csrc = (const int*)d_in[14];
    const int* cdst = (const int*)d_in[15];
    const int* esrc = (const int*)d_in[16];
    const int* edst = (const int*)d_in[17];
    float* out = (float*)d_out;

    bf* xaH[2] = {sym_addr<bf>(g_xaH), sym_addr<bf>(g_xaH) + (size_t)NA * CD};
    bf* xaL[2] = {sym_addr<bf>(g_xaL), sym_addr<bf>(g_xaL) + (size_t)NA * CD};
    bf* xpH[2] = {sym_addr<bf>(g_xpH), sym_addr<bf>(g_xpH) + (size_t)NP * CD};
    bf* xpL[2] = {sym_addr<bf>(g_xpL), sym_addr<bf>(g_xpL) + (size_t)NP * CD};
    float* xaF[2] = {sym_addr<float>(g_xaF), sym_addr<float>(g_xaF) + (size_t)NA * CD};
    float* xpF[2] = {sym_addr<float>(g_xpF), sym_addr<float>(g_xpF) + (size_t)NP * CD};
    bf* aWH = sym_addr<bf>(g_aWH); bf* aWL = sym_addr<bf>(g_aWL);
    bf* aCH = sym_addr<bf>(g_aCH); bf* aCL = sym_addr<bf>(g_aCL);
    bf* aAH = sym_addr<bf>(g_aAH); bf* aAL = sym_addr<bf>(g_aAL);
    bf* xinAH = sym_addr<bf>(g_xinAH); bf* xinAL = sym_addr<bf>(g_xinAL);
    bf* xinPH = sym_addr<bf>(g_xinPH); bf* xinPL = sym_addr<bf>(g_xinPL);
    bf* BP1h = sym_addr<bf>(g_BP1h); bf* BP1l = sym_addr<bf>(g_BP1l);
    bf* BA1h = sym_addr<bf>(g_BA1h); bf* BA1l = sym_addr<bf>(g_BA1l);
    bf* BPh3 = sym_addr<bf>(g_BPh3); bf* BPl3 = sym_addr<bf>(g_BPl3);
    bf* BAh3 = sym_addr<bf>(g_BAh3); bf* BAl3 = sym_addr<bf>(g_BAl3);
    bf* BDh = sym_addr<bf>(g_BDh); bf* BDl = sym_addr<bf>(g_BDl);
    float* bc = sym_addr<float>(g_bc);
    float* TB = sym_addr<float>(g_TB);
    int* rpW = sym_addr<int>(g_rpW);
    int* rpC = sym_addr<int>(g_rpC);
    int* rpA = sym_addr<int>(g_rpA);
    int* colW = sym_addr<int>(g_colW);
    int* colC = sym_addr<int>(g_colC);
    int* colA = sym_addr<int>(g_colA);
    int* cnt = sym_addr<int>(g_cnt);

    cudaFuncSetAttribute(k_mgemm2, cudaFuncAttributeMaxDynamicSharedMemorySize, SMEM_TOTAL);

    const int TPB = 256;
    const int nbP = (NP + 7) / 8;
    const int nbA = (NA + 7) / 8;

    // ---- Front: zero counters; [hist+prep]; [scan+split+fill] ----
    cudaMemsetAsync(cnt, 0, (2 * NP + NA) * sizeof(int));
    k_front1<<<HIST_B + PREP_B, TPB>>>(wdst, cdst, wsrc, Wl1, bl1, Wr1,
                                       Wl, bl, Wr, dec_W1);
    k_front2<<<3 + SPLIT_B + NFILL2, 1024>>>(x_author, x_paper,
                                             wdst, wsrc, cdst, csrc);

    AggJob jW, jC, jA;
    jW.rp = rpW; jW.col = colW; jW.oh = aWH; jW.ol = aWL; jW.ndst = NP;
    jC.rp = rpC; jC.col = colC; jC.oh = aCH; jC.ol = aCL; jC.ndst = NP;
    jA.rp = rpA; jA.col = colA; jA.oh = aAH; jA.ol = aAL; jA.ndst = NA;

    GemmP gp, ga;
    gp.Nall = 256; ga.Nall = 256;
    gp.Cf = nullptr; ga.Cf = nullptr;
    gp.A0h = aWH; gp.A0l = aWL; gp.A1h = aCH; gp.A1l = aCL;
    gp.M = NP;
    ga.A0h = aAH; ga.A0l = aAL; ga.A2h = nullptr; ga.A2l = nullptr;
    ga.M = NA;

    const int yP = (NP + 127) / 128;   // 782
    const int yA = (NA + 127) / 128;   // 391
    dim3 gridPA(4, yP + yA);
    dim3 gridD(8, yA);

    // ---- Layer 1 (Kseg = 128): agg reads raw fp32 inputs ----
    jW.xf = x_author;
    jC.xf = x_paper;
    jA.xf = x_paper;
    k_agg3<128><<<2 * nbP + nbA, TPB>>>(jW, jC, jA, nbP, nbP, nbA);
    gp.Ktot = 384; gp.Kseg = 128; gp.relu = 1;
    gp.A2h = xinPH; gp.A2l = xinPL;
    gp.Bh = BP1h; gp.Bl = BP1l; gp.bias = bc;
    gp.Ch = xpH[0]; gp.Cl = xpL[0]; gp.Cx = xpF[0];
    ga.Ktot = 256; ga.Kseg = 128; ga.relu = 1;
    ga.A1h = xinAH; ga.A1l = xinAL;
    ga.Bh = BA1h; ga.Bl = BA1l; ga.bias = bl1 + 256;
    ga.Ch = xaH[0]; ga.Cl = xaL[0]; ga.Cx = xaF[0];
    k_mgemm2<<<gridPA, TPB, SMEM_TOTAL>>>(gp, ga, yP);   // profiled (#4)

    // ---- Layers 2..4 (Kseg = 256) ----
    int cur = 0;
    for (int l = 0; l < 3; l++) {
        jW.xf = xaF[cur];
        jC.xf = xpF[cur];
        jA.xf = xpF[cur];
        k_agg3<256><<<2 * nbP + nbA, TPB>>>(jW, jC, jA, nbP, nbP, nbA);
        int relu = (l < 2) ? 1 : 0;
        int needF = (l < 2) ? 1 : 0;   // layer-4 output feeds decoder only
        gp.Ktot = 768; gp.Kseg = 256; gp.relu = relu;
        gp.A2h = xpH[cur]; gp.A2l = xpL[cur];
        gp.Bh = BPh3 + (size_t)l * 256 * 768;
        gp.Bl = BPl3 + (size_t)l * 256 * 768;
        gp.bias = bc + (l + 1) * 256;
        gp.Ch = xpH[1 - cur]; gp.Cl = xpL[1 - cur];
        gp.Cx = needF ? xpF[1 - cur] : nullptr;
        ga.Ktot = 512; ga.Kseg = 256; ga.relu = relu;
        ga.A1h = xaH[cur]; ga.A1l = xaL[cur];
        ga.Bh = BAh3 + (size_t)l * 256 * 512;
        ga.Bl = BAl3 + (size_t)l * 256 * 512;
        ga.bias = bl + l * 768 + 256;
        ga.Ch = xaH[1 - cur]; ga.Cl = xaL[1 - cur];
        ga.Cx = needF ? xaF[1 - cur] : nullptr;
        k_mgemm2<<<gridPA, TPB, SMEM_TOTAL>>>(gp, ga, yP);
        cur ^= 1;
    }

    // ---- Decoder ----
    GemmP gd;
    gd.M = NA; gd.Ktot = 256; gd.Kseg = 256; gd.Nall = 512; gd.relu = 0;
    gd.A0h = xaH[cur]; gd.A0l = xaL[cur];
    gd.A1h = nullptr; gd.A1l = nullptr; gd.A2h = nullptr; gd.A2l = nullptr;
    gd.Bh = BDh; gd.Bl = BDl; gd.bias = nullptr;
    gd.Cf = TB; gd.Ch = nullptr; gd.Cl = nullptr; gd.Cx = nullptr;
    k_mgemm2<<<gridD, TPB, SMEM_TOTAL>>>(gd, gd, yA + 1);
    k_edge<<<(NEL * 32 + TPB - 1) / TPB, TPB>>>(esrc, edst, TB, dec_b1, dec_W2,
                                                dec_b2, out);
}

// round 17
// speedup vs baseline: 1.0477x; 1.0477x over previous
#include <cuda_runtime.h>
#include <cuda_bf16.h>
#include <cstdint>
#include <cstddef>

// ---------------------------------------------------------------------------
// Problem constants
// ---------------------------------------------------------------------------
#define NA   50000
#define NP   100000
#define NE   800000
#define NEL  100000
#define CD   256

typedef __nv_bfloat16 bf;

// ---------------------------------------------------------------------------
// Device scratch
// ---------------------------------------------------------------------------
__device__ bf g_xaH[2][(size_t)NA * CD];
__device__ bf g_xaL[2][(size_t)NA * CD];
__device__ bf g_xpH[2][(size_t)NP * CD];
__device__ bf g_xpL[2][(size_t)NP * CD];
__device__ float g_xaF[2][(size_t)NA * CD];   // fp32 activation copies (agg input)
__device__ float g_xpF[2][(size_t)NP * CD];
__device__ bf g_aWH[(size_t)NP * CD];
__device__ bf g_aWL[(size_t)NP * CD];
__device__ bf g_aCH[(size_t)NP * CD];
__device__ bf g_aCL[(size_t)NP * CD];
__device__ bf g_aAH[(size_t)NA * CD];
__device__ bf g_aAL[(size_t)NA * CD];
__device__ bf g_xinAH[(size_t)NA * 128];
__device__ bf g_xinAL[(size_t)NA * 128];
__device__ bf g_xinPH[(size_t)NP * 128];
__device__ bf g_xinPL[(size_t)NP * 128];
// Per-layer prepped weight planes
__device__ bf g_BP1h[256 * 384];
__device__ bf g_BP1l[256 * 384];
__device__ bf g_BA1h[256 * 256];
__device__ bf g_BA1l[256 * 256];
__device__ bf g_BPh3[3][256 * 768];
__device__ bf g_BPl3[3][256 * 768];
__device__ bf g_BAh3[3][256 * 512];
__device__ bf g_BAl3[3][256 * 512];
__device__ bf g_BDh[512 * 256];
__device__ bf g_BDl[512 * 256];
__device__ float g_bc[4][256];
__device__ float g_TB[(size_t)NA * 512];
// CSR
__device__ int g_rpW[NP + 1];
__device__ int g_rpC[NP + 1];
__device__ int g_rpA[NA + 1];
__device__ int g_colW[NE];
__device__ int g_colC[NE];
__device__ int g_colA[NE];
__device__ int g_cnt[2 * NP + NA];   // [W | C | A]

// ---------------------------------------------------------------------------
// Baseline-PTX helpers (sm_80+: mma.sync bf16, ldmatrix, cp.async; sm_100: f32x2)
// ---------------------------------------------------------------------------
__device__ __forceinline__ uint32_t smem_u32(const void* p) {
    uint32_t a;
    asm("{ .reg .u64 t; cvta.to.shared.u64 t, %1; cvt.u32.u64 %0, t; }"
        : "=r"(a) : "l"(p));
    return a;
}
__device__ __forceinline__ void cpasync16(uint32_t dst, const void* src, int sz) {
    asm volatile("cp.async.cg.shared.global [%0], [%1], 16, %2;"
                 :: "r"(dst), "l"(src), "r"(sz) : "memory");
}
#define CP_COMMIT() asm volatile("cp.async.commit_group;" ::: "memory")
#define CP_WAIT0()  asm volatile("cp.async.wait_group 0;" ::: "memory")

__device__ __forceinline__ void ldsm4(uint32_t* r, uint32_t addr) {
    asm volatile("ldmatrix.sync.aligned.m8n8.x4.shared.b16 {%0,%1,%2,%3}, [%4];"
                 : "=r"(r[0]), "=r"(r[1]), "=r"(r[2]), "=r"(r[3]) : "r"(addr));
}
__device__ __forceinline__ void mma16816(float* c, const uint32_t* a, const uint32_t* b) {
    asm volatile(
        "mma.sync.aligned.m16n8k16.row.col.f32.bf16.bf16.f32 "
        "{%0,%1,%2,%3}, {%4,%5,%6,%7}, {%8,%9}, {%0,%1,%2,%3};"
        : "+f"(c[0]), "+f"(c[1]), "+f"(c[2]), "+f"(c[3])
        : "r"(a[0]), "r"(a[1]), "r"(a[2]), "r"(a[3]), "r"(b[0]), "r"(b[1]));
}
// Packed fp32x2 add (PTX ISA sm_100+, NOT sm_100a-gated)
__device__ __forceinline__ unsigned long long addf32x2(unsigned long long a,
                                                       unsigned long long b) {
    unsigned long long c;
    asm("add.rn.f32x2 %0, %1, %2;" : "=l"(c) : "l"(a), "l"(b));
    return c;
}

// ---------------------------------------------------------------------------
// Split-precision helpers
// ---------------------------------------------------------------------------
__device__ __forceinline__ void split1(float v, bf& h, bf& l) {
    h = __float2bfloat16(v);
    l = __float2bfloat16(v - __bfloat162float(h));
}
__device__ __forceinline__ uint32_t packbf2(bf a, bf b) {
    __nv_bfloat162 p = __halves2bfloat162(a, b);
    return *reinterpret_cast<uint32_t*>(&p);
}

// ---------------------------------------------------------------------------
// Front kernel 1: histogram + ALL weight/bias prep (block-range dispatch)
// ---------------------------------------------------------------------------
__device__ void hist_body(const int* __restrict__ wdst, const int* __restrict__ cdst,
                          const int* __restrict__ wsrc, int rb, int nb) {
    int* cW = g_cnt;
    int* cC = g_cnt + NP;
    int* cA = g_cnt + 2 * NP;
    for (int e = rb * blockDim.x + threadIdx.x; e < NE; e += nb * blockDim.x) {
        atomicAdd(&cW[wdst[e]], 1);
        atomicAdd(&cC[cdst[e]], 1);
        atomicAdd(&cA[wsrc[e]], 1);
    }
}

__device__ __forceinline__ void prep_emit(int j, int Ktot, int Kseg,
                                          const float* W0, const float* W1s,
                                          const float* W2a, const float* W2b,
                                          bf* Bh, bf* Bl) {
    int n = j / Ktot, kg = j - n * Ktot;
    int seg = kg / Kseg, k = kg - seg * Kseg;
    float v;
    if (seg == 0)      v = W0[k * 256 + n];
    else if (seg == 1) v = W1s[k * 256 + n];
    else               v = W2a[k * 256 + n] + W2b[k * 256 + n];
    bf h, l;
    split1(v, h, l);
    Bh[j] = h;
    Bl[j] = l;
}

#define P1_SZ  98304     // 256*384
#define PL_SZ  196608    // 256*768
#define A1_SZ  65536     // 256*256
#define AL_SZ  131072    // 256*512
#define DEC_SZ 131072    // 512*256
#define PREP_TOT (P1_SZ + 3 * PL_SZ + A1_SZ + 3 * AL_SZ + DEC_SZ + 1024)

__device__ void prep_body(const float* Wl1, const float* bl1, const float* Wr1,
                          const float* Wl, const float* bl, const float* Wr,
                          const float* dW1, int rb, int nb) {
    for (int i = rb * blockDim.x + threadIdx.x; i < PREP_TOT; i += nb * blockDim.x) {
        int r = i;
        if (r < P1_SZ) {
            prep_emit(r, 384, 128, Wl1, Wl1 + 2 * 32768, Wr1, Wr1 + 2 * 32768,
                      g_BP1h, g_BP1l);
            continue;
        }
        r -= P1_SZ;
        if (r < 3 * PL_SZ) {
            int l = r / PL_SZ, j = r - l * PL_SZ;
            const float* Wl_l = Wl + (size_t)l * 3 * 65536;
            const float* Wr_l = Wr + (size_t)l * 3 * 65536;
            prep_emit(j, 768, 256, Wl_l, Wl_l + 2 * 65536, Wr_l, Wr_l + 2 * 65536,
                      g_BPh3[l], g_BPl3[l]);
            continue;
        }
        r -= 3 * PL_SZ;
        if (r < A1_SZ) {
            prep_emit(r, 256, 128, Wl1 + 32768, Wr1 + 32768, nullptr, nullptr,
                      g_BA1h, g_BA1l);
            continue;
        }
        r -= A1_SZ;
        if (r < 3 * AL_SZ) {
            int l = r / AL_SZ, j = r - l * AL_SZ;
            const float* Wl_l = Wl + (size_t)l * 3 * 65536;
            const float* Wr_l = Wr + (size_t)l * 3 * 65536;
            prep_emit(j, 512, 256, Wl_l + 65536, Wr_l + 65536, nullptr, nullptr,
                      g_BAh3[l], g_BAl3[l]);
            continue;
        }
        r -= 3 * AL_SZ;
        if (r < DEC_SZ) {
            int n = r >> 8, k = r & 255;
            float v = (n < 256) ? dW1[k * 256 + n] : dW1[(256 + k) * 256 + (n - 256)];
            bf h, l;
            split1(v, h, l);
            g_BDh[r] = h;
            g_BDl[r] = l;
            continue;
        }
        r -= DEC_SZ;
        if (r < 256) {
            g_bc[0][r] = bl1[r] + bl1[512 + r];
        } else if (r < 1024) {
            int l = (r - 256) >> 8, c = r & 255;
            g_bc[l + 1][c] = bl[l * 768 + c] + bl[l * 768 + 512 + c];
        }
    }
}

#define HIST_B 1024
#define PREP_B 512
__global__ void k_front1(const int* __restrict__ wdst, const int* __restrict__ cdst,
                         const int* __restrict__ wsrc,
                         const float* __restrict__ Wl1, const float* __restrict__ bl1,
                         const float* __restrict__ Wr1,
                         const float* __restrict__ Wl, const float* __restrict__ bl,
                         const float* __restrict__ Wr, const float* __restrict__ dW1) {
    int b = blockIdx.x;
    if (b < HIST_B) hist_body(wdst, cdst, wsrc, b, HIST_B);
    else            prep_body(Wl1, bl1, Wr1, Wl, bl, Wr, dW1, b - HIST_B, PREP_B);
}

// ---------------------------------------------------------------------------
// Front kernel 2: merged scan (3 blocks, 16 elems/thread, zero-on-read) +
// input split (remaining blocks). 1024 threads per block.
// ---------------------------------------------------------------------------
__device__ void scan_body(int* __restrict__ cnt, int* __restrict__ rp, int n) {
    __shared__ int wsum[32];
    __shared__ int carry;
    int t = threadIdx.x, lane = t & 31, wid = t >> 5;
    if (t == 0) carry = 0;
    __syncthreads();
    const int TILE = 1024 * 16;
    for (int base = 0; base < n; base += TILE) {
        int idx0 = base + t * 16;
        int v[16];
        int tot = 0;
        if (idx0 < n) {
            int4* p = (int4*)(cnt + idx0);
            int4 a0 = p[0], a1 = p[1], a2 = p[2], a3 = p[3];
            v[0] = a0.x;  v[1] = a0.y;  v[2] = a0.z;  v[3] = a0.w;
            v[4] = a1.x;  v[5] = a1.y;  v[6] = a1.z;  v[7] = a1.w;
            v[8] = a2.x;  v[9] = a2.y;  v[10] = a2.z; v[11] = a2.w;
            v[12] = a3.x; v[13] = a3.y; v[14] = a3.z; v[15] = a3.w;
            #pragma unroll
            for (int j = 0; j < 16; j++) tot += v[j];
            int4 z = make_int4(0, 0, 0, 0);
            p[0] = z; p[1] = z; p[2] = z; p[3] = z;
        } else {
            #pragma unroll
            for (int j = 0; j < 16; j++) v[j] = 0;
        }
        int x = tot;
        #pragma unroll
        for (int off = 1; off < 32; off <<= 1) {
            int y = __shfl_up_sync(0xffffffffu, x, off);
            if (lane >= off) x += y;
        }
        if (lane == 31) wsum[wid] = x;
        __syncthreads();
        if (wid == 0) {
            int s = wsum[lane];
            #pragma unroll
            for (int off = 1; off < 32; off <<= 1) {
                int y = __shfl_up_sync(0xffffffffu, s, off);
                if (lane >= off) s += y;
            }
            wsum[lane] = s;
        }
        __syncthreads();
        if (idx0 < n) {
            int run = ((wid > 0) ? wsum[wid - 1] : 0) + carry + x - tot;  // exclusive
            int o[16];
            #pragma unroll
            for (int j = 0; j < 16; j++) { o[j] = run; run += v[j]; }
            int4* q = (int4*)(rp + idx0);
            q[0] = make_int4(o[0], o[1], o[2], o[3]);
            q[1] = make_int4(o[4], o[5], o[6], o[7]);
            q[2] = make_int4(o[8], o[9], o[10], o[11]);
            q[3] = make_int4(o[12], o[13], o[14], o[15]);
        }
        __syncthreads();
        if (t == 0) carry += wsum[31];
        __syncthreads();
    }
    if (t == 0) rp[n] = carry;
}

__device__ void split_body(const float* __restrict__ xa, const float* __restrict__ xp,
                           int rb, int nb) {
    const int n1 = NA * 128, n2 = NP * 128;
    for (int i = rb * blockDim.x + threadIdx.x; i < n1 + n2; i += nb * blockDim.x) {
        bf h, l;
        if (i < n1) {
            split1(xa[i], h, l);
            g_xinAH[i] = h; g_xinAL[i] = l;
        } else {
            int j = i - n1;
            split1(xp[j], h, l);
            g_xinPH[j] = h; g_xinPL[j] = l;
        }
    }
}

#define SPLIT_B 512
__global__ void k_front2(const float* __restrict__ xa, const float* __restrict__ xp) {
    int b = blockIdx.x;
    if (b == 0)      scan_body(g_cnt,          g_rpW, NP);
    else if (b == 1) scan_body(g_cnt + NP,     g_rpC, NP);
    else if (b == 2) scan_body(g_cnt + 2 * NP, g_rpA, NA);
    else             split_body(xa, xp, b - 3, SPLIT_B);
}

// ---------------------------------------------------------------------------
// Merged CSR fill
// ---------------------------------------------------------------------------
__device__ void fill_body(const int* __restrict__ key, const int* __restrict__ val,
                          const int* __restrict__ rp, int* __restrict__ cur,
                          int* __restrict__ col, int rb, int nb) {
    for (int e = rb * blockDim.x + threadIdx.x; e < NE; e += nb * blockDim.x) {
        int k = key[e];
        int pos = rp[k] + atomicAdd(&cur[k], 1);
        col[pos] = val[e];
    }
}

#define FILLB 512
__global__ void k_fill3(const int* __restrict__ wdst, const int* __restrict__ wsrc,
                        const int* __restrict__ cdst, const int* __restrict__ csrc) {
    int job = blockIdx.x / FILLB, rb = blockIdx.x % FILLB;
    if (job == 0)      fill_body(wdst, wsrc, g_rpW, g_cnt,          g_colW, rb, FILLB);
    else if (job == 1) fill_body(cdst, csrc, g_rpC, g_cnt + NP,     g_colC, rb, FILLB);
    else               fill_body(wsrc, wdst, g_rpA, g_cnt + 2 * NP, g_colA, rb, FILLB);
}

// ---------------------------------------------------------------------------
// Merged mean aggregation: 3 jobs, fp32 gather input, f32x2 SIMD accumulate.
// ---------------------------------------------------------------------------
struct AggJob {
    const float* xf;
    const int *rp, *col;
    bf *oh, *ol;
    int ndst;
};

template <int DIM>
__device__ void agg_body(const AggJob& J, int rb, int nb) {
    constexpr int EPL = DIM / 32;   // 4 or 8 floats per lane
    constexpr int W = EPL / 2;      // 2 or 4 f32x2 words
    int lane = threadIdx.x & 31;
    int w  = rb * (blockDim.x >> 5) + (threadIdx.x >> 5);
    int nw = nb * (blockDim.x >> 5);
    const float* x0 = J.xf + lane * EPL;
    const int* __restrict__ col = J.col;
    for (int d = w; d < J.ndst; d += nw) {
        int e0 = J.rp[d], e1 = J.rp[d + 1];
        unsigned long long acc2[W];
        #pragma unroll
        for (int j = 0; j < W; j++) acc2[j] = 0ull;
        for (int e = e0; e < e1; e++) {
            int off = col[e] * DIM;              // < 2^25, fits int
            unsigned long long v[W];
            if (W == 4) {
                *(ulonglong4*)v = *(const ulonglong4*)(x0 + off);
            } else {
                *(ulonglong2*)v = *(const ulonglong2*)(x0 + off);
            }
            #pragma unroll
            for (int j = 0; j < W; j++) acc2[j] = addf32x2(acc2[j], v[j]);
        }
        float inv = 1.0f / (float)max(e1 - e0, 1);
        uint32_t ohw[W], olw[W];
        #pragma unroll
        for (int j = 0; j < W; j++) {
            float v0 = __uint_as_float((uint32_t)acc2[j]) * inv;
            float v1 = __uint_as_float((uint32_t)(acc2[j] >> 32)) * inv;
            bf h0, l0, h1, l1;
            split1(v0, h0, l0);
            split1(v1, h1, l1);
            ohw[j] = packbf2(h0, h1);
            olw[j] = packbf2(l0, l1);
        }
        size_t obase = (size_t)d * DIM + lane * EPL;
        if (W == 4) {
            *(uint4*)(J.oh + obase) = *(uint4*)ohw;
            *(uint4*)(J.ol + obase) = *(uint4*)olw;
        } else {
            *(uint2*)(J.oh + obase) = *(uint2*)ohw;
            *(uint2*)(J.ol + obase) = *(uint2*)olw;
        }
    }
}

template <int DIM>
__global__ void k_agg3(AggJob j0, AggJob j1, AggJob j2, int nb0, int nb1, int nb2) {
    int b = blockIdx.x;
    if (b < nb0)            agg_body<DIM>(j0, b, nb0);
    else if (b < nb0 + nb1) agg_body<DIM>(j1, b - nb0, nb1);
    else                    agg_body<DIM>(j2, b - nb0 - nb1, nb2);
}

// ---------------------------------------------------------------------------
// Split-bf16 tensor-core GEMM (mma.sync m16n8k16, cp.async double buffer)
// Block tile 128x128, warp tile 64x32 (best measured config).
// Single-barrier pipeline: wait0 -> sync -> issue load(s+1) -> compute(s).
// ---------------------------------------------------------------------------
#define ROWB   80
#define OFF_AH 0
#define OFF_AL 10240
#define OFF_BH 20480
#define OFF_BL 30720
#define STAGE  40960
#define SMEM_TOTAL (2 * STAGE)

struct GemmP {
    int M, Ktot, Kseg, Nall, relu;
    const bf *A0h, *A0l, *A1h, *A1l, *A2h, *A2l, *Bh, *Bl;
    const float* bias;
    float* Cf;
    bf *Ch, *Cl;
    float* Cx;
};

__device__ __forceinline__ void stage_load(const GemmP& P, uint32_t sb, int stg,
                                           int tid, int bm, int n_off, int s) {
    int kg = s * 32;
    int seg = kg / P.Kseg;
    int kof = kg - seg * P.Kseg;
    const bf* ah = (seg == 0) ? P.A0h : (seg == 1) ? P.A1h : P.A2h;
    const bf* al = (seg == 0) ? P.A0l : (seg == 1) ? P.A1l : P.A2l;
    uint32_t base = sb + stg * STAGE;
    #pragma unroll
    for (int i = 0; i < 2; i++) {
        int c = tid + 256 * i;
        int row = c >> 2, kc = c & 3;
        uint32_t d = base + row * ROWB + kc * 16;
        int gr = bm + row;
        int sz = (gr < P.M) ? 16 : 0;
        int grc = (gr < P.M) ? gr : (P.M - 1);
        size_t aoff = (size_t)grc * P.Kseg + kof + kc * 8;
        cpasync16(d + OFF_AH, ah + aoff, sz);
        cpasync16(d + OFF_AL, al + aoff, sz);
        size_t boff = (size_t)(n_off + row) * P.Ktot + kg + kc * 8;
        cpasync16(d + OFF_BH, P.Bh + boff, 16);
        cpasync16(d + OFF_BL, P.Bl + boff, 16);
    }
}

__global__ void __launch_bounds__(256, 2)
k_mgemm2(GemmP p, GemmP q, int yP) {
    extern __shared__ char smem[];
    uint32_t sb = smem_u32(smem);
    int tid = threadIdx.x;
    int lane = tid & 31;
    int warp = tid >> 5;
    int wm = warp >> 2;
    int wn = warp & 3;

    GemmP P;
    int by = blockIdx.y;
    if (by < yP) P = p;
    else { P = q; by -= yP; }
    int bm = by * 128;
    int n_off = blockIdx.x * 128;
    int S = P.Ktot / 32;

    float acc[4][4][4];
    #pragma unroll
    for (int a = 0; a < 4; a++)
        #pragma unroll
        for (int b = 0; b < 4; b++)
            #pragma unroll
            for (int c = 0; c < 4; c++) acc[a][b][c] = 0.f;

    uint32_t lmo = (uint32_t)((lane & 15) * ROWB + (lane >> 4) * 16);

    stage_load(P, sb, 0, tid, bm, n_off, 0);
    CP_COMMIT();

    for (int s = 0; s < S; s++) {
        CP_WAIT0();            // stage s landed (single group in flight)
        __syncthreads();       // all warps done with compute(s-1) AND see stage s
        if (s + 1 < S) {
            stage_load(P, sb, (s + 1) & 1, tid, bm, n_off, s + 1);
            CP_COMMIT();       // overlaps with compute(s) below
        }

        uint32_t base = sb + (s & 1) * STAGE;
        #pragma unroll
        for (int ks = 0; ks < 2; ks++) {
            uint32_t kb = ks * 32;
            uint32_t af[4][4], bhf[4][2], blf[4][2];
            #pragma unroll
            for (int mt = 0; mt < 4; mt++)
                ldsm4(af[mt], base + OFF_AH + (wm * 64 + mt * 16) * ROWB + kb + lmo);
            #pragma unroll
            for (int bt = 0; bt < 2; bt++) {
                uint32_t r[4];
                ldsm4(r, base + OFF_BH + (wn * 32 + bt * 16) * ROWB + kb + lmo);
                bhf[2 * bt][0] = r[0]; bhf[2 * bt][1] = r[2];
                bhf[2 * bt + 1][0] = r[1]; bhf[2 * bt + 1][1] = r[3];
            }
            #pragma unroll
            for (int bt = 0; bt < 2; bt++) {
                uint32_t r[4];
                ldsm4(r, base + OFF_BL + (wn * 32 + bt * 16) * ROWB + kb + lmo);
                blf[2 * bt][0] = r[0]; blf[2 * bt][1] = r[2];
                blf[2 * bt + 1][0] = r[1]; blf[2 * bt + 1][1] = r[3];
            }
            #pragma unroll
            for (int mt = 0; mt < 4; mt++)
                #pragma unroll
                for (int nt = 0; nt < 4; nt++) mma16816(acc[mt][nt], af[mt], bhf[nt]);
            #pragma unroll
            for (int mt = 0; mt < 4; mt++)
                #pragma unroll
                for (int nt = 0; nt < 4; nt++) mma16816(acc[mt][nt], af[mt], blf[nt]);
            #pragma unroll
            for (int mt = 0; mt < 4; mt++)
                ldsm4(af[mt], base + OFF_AL + (wm * 64 + mt * 16) * ROWB + kb + lmo);
            #pragma unroll
            for (int mt = 0; mt < 4; mt++)
                #pragma unroll
                for (int nt = 0; nt < 4; nt++) mma16816(acc[mt][nt], af[mt], bhf[nt]);
        }
        // no trailing barrier: next iteration's sync (after wait0) protects reuse
    }

    // Epilogue
    #pragma unroll
    for (int mt = 0; mt < 4; mt++) {
        int r0 = bm + wm * 64 + mt * 16 + (lane >> 2);
        #pragma unroll
        for (int half = 0; half < 2; half++) {
            int row = r0 + half * 8;
            if (row >= P.M) continue;
            #pragma unroll
            for (int nt = 0; nt < 4; nt++) {
                int gcol = n_off + wn * 32 + nt * 8 + (lane & 3) * 2;
                float v0 = acc[mt][nt][half * 2 + 0];
                float v1 = acc[mt][nt][half * 2 + 1];
                if (P.Cf) {
                    *(float2*)(P.Cf + (size_t)row * P.Nall + gcol) = make_float2(v0, v1);
                } else {
                    v0 += P.bias[gcol];
                    v1 += P.bias[gcol + 1];
                    if (P.relu) { v0 = fmaxf(v0, 0.f); v1 = fmaxf(v1, 0.f); }
                    if (P.Cx)
                        *(float2*)(P.Cx + (size_t)row * P.Nall + gcol) = make_float2(v0, v1);
                    bf h0, l0, h1, l1;
                    split1(v0, h0, l0);
                    split1(v1, h1, l1);
                    *(uint32_t*)(P.Ch + (size_t)row * P.Nall + gcol) = packbf2(h0, h1);
                    *(uint32_t*)(P.Cl + (size_t)row * P.Nall + gcol) = packbf2(l0, l1);
                }
            }
        }
    }
}

// ---------------------------------------------------------------------------
// Fused edge decoder
// ---------------------------------------------------------------------------
__global__ void k_edge(const int* __restrict__ src, const int* __restrict__ dst,
                       const float* __restrict__ TB, const float* __restrict__ b1,
                       const float* __restrict__ W2, const float* __restrict__ b2,
                       float* __restrict__ out) {
    int lane = threadIdx.x & 31;
    int w  = (blockIdx.x * blockDim.x + threadIdx.x) >> 5;
    int nw = (gridDim.x * blockDim.x) >> 5;
    for (int e = w; e < NEL; e += nw) {
        int s = src[e], d = dst[e];
        const float* Ts = TB + (size_t)s * 512;
        const float* Td = TB + (size_t)d * 512 + 256;
        float sum = 0.f;
        #pragma unroll
        for (int k = 0; k < 8; k++) {
            int c = lane + 32 * k;
            float h = Ts[c] + Td[c] + b1[c];
            h = fmaxf(h, 0.f);
            sum += h * W2[c];
        }
        #pragma unroll
        for (int off = 16; off; off >>= 1)
            sum += __shfl_down_sync(0xffffffffu, sum, off);
        if (lane == 0) out[e] = sum + b2[0];
    }
}

// ---------------------------------------------------------------------------
// Host
// ---------------------------------------------------------------------------
template <typename T>
static T* sym_addr(const void* sym) {
    void* p = nullptr;
    cudaGetSymbolAddress(&p, sym);
    return (T*)p;
}

extern "C" void kernel_launch(void* const* d_in, const int* in_sizes, int n_in,
                              void* d_out, int out_size) {
    const float* x_author = (const float*)d_in[0];
    const float* x_paper  = (const float*)d_in[1];
    const float* Wl1      = (const float*)d_in[2];
    const float* bl1      = (const float*)d_in[3];
    const float* Wr1      = (const float*)d_in[4];
    const float* Wl       = (const float*)d_in[5];
    const float* bl       = (const float*)d_in[6];
    const float* Wr       = (const float*)d_in[7];
    const float* dec_W1   = (const float*)d_in[8];
    const float* dec_b1   = (const float*)d_in[9];
    const float* dec_W2   = (const float*)d_in[10];
    const float* dec_b2   = (const float*)d_in[11];
    const int* wsrc = (const int*)d_in[12];
    const int* wdst = (const int*)d_in[13];
    const int* csrc = (const int*)d_in[14];
    const int* cdst = (const int*)d_in[15];
    const int* esrc = (const int*)d_in[16];
    const int* edst = (const int*)d_in[17];
    float* out = (float*)d_out;

    bf* xaH[2] = {sym_addr<bf>(g_xaH), sym_addr<bf>(g_xaH) + (size_t)NA * CD};
    bf* xaL[2] = {sym_addr<bf>(g_xaL), sym_addr<bf>(g_xaL) + (size_t)NA * CD};
    bf* xpH[2] = {sym_addr<bf>(g_xpH), sym_addr<bf>(g_xpH) + (size_t)NP * CD};
    bf* xpL[2] = {sym_addr<bf>(g_xpL), sym_addr<bf>(g_xpL) + (size_t)NP * CD};
    float* xaF[2] = {sym_addr<float>(g_xaF), sym_addr<float>(g_xaF) + (size_t)NA * CD};
    float* xpF[2] = {sym_addr<float>(g_xpF), sym_addr<float>(g_xpF) + (size_t)NP * CD};
    bf* aWH = sym_addr<bf>(g_aWH); bf* aWL = sym_addr<bf>(g_aWL);
    bf* aCH = sym_addr<bf>(g_aCH); bf* aCL = sym_addr<bf>(g_aCL);
    bf* aAH = sym_addr<bf>(g_aAH); bf* aAL = sym_addr<bf>(g_aAL);
    bf* xinAH = sym_addr<bf>(g_xinAH); bf* xinAL = sym_addr<bf>(g_xinAL);
    bf* xinPH = sym_addr<bf>(g_xinPH); bf* xinPL = sym_addr<bf>(g_xinPL);
    bf* BP1h = sym_addr<bf>(g_BP1h); bf* BP1l = sym_addr<bf>(g_BP1l);
    bf* BA1h = sym_addr<bf>(g_BA1h); bf* BA1l = sym_addr<bf>(g_BA1l);
    bf* BPh3 = sym_addr<bf>(g_BPh3); bf* BPl3 = sym_addr<bf>(g_BPl3);
    bf* BAh3 = sym_addr<bf>(g_BAh3); bf* BAl3 = sym_addr<bf>(g_BAl3);
    bf* BDh = sym_addr<bf>(g_BDh); bf* BDl = sym_addr<bf>(g_BDl);
    float* bc = sym_addr<float>(g_bc);
    float* TB = sym_addr<float>(g_TB);
    int* rpW = sym_addr<int>(g_rpW);
    int* rpC = sym_addr<int>(g_rpC);
    int* rpA = sym_addr<int>(g_rpA);
    int* colW = sym_addr<int>(g_colW);
    int* colC = sym_addr<int>(g_colC);
    int* colA = sym_addr<int>(g_colA);
    int* cnt = sym_addr<int>(g_cnt);

    cudaFuncSetAttribute(k_mgemm2, cudaFuncAttributeMaxDynamicSharedMemorySize, SMEM_TOTAL);

    const int TPB = 256;
    const int nbP = (NP + 7) / 8;
    const int nbA = (NA + 7) / 8;

    // ---- Front: zero counters; [hist+prep]; [scan+split]; fill ----
    cudaMemsetAsync(cnt, 0, (2 * NP + NA) * sizeof(int));
    k_front1<<<HIST_B + PREP_B, TPB>>>(wdst, cdst, wsrc, Wl1, bl1, Wr1,
                                       Wl, bl, Wr, dec_W1);
    k_front2<<<3 + SPLIT_B, 1024>>>(x_author, x_paper);
    k_fill3<<<3 * FILLB, TPB>>>(wdst, wsrc, cdst, csrc);

    AggJob jW, jC, jA;
    jW.rp = rpW; jW.col = colW; jW.oh = aWH; jW.ol = aWL; jW.ndst = NP;
    jC.rp = rpC; jC.col = colC; jC.oh = aCH; jC.ol = aCL; jC.ndst = NP;
    jA.rp = rpA; jA.col = colA; jA.oh = aAH; jA.ol = aAL; jA.ndst = NA;

    GemmP gp, ga;
    gp.Nall = 256; ga.Nall = 256;
    gp.Cf = nullptr; ga.Cf = nullptr;
    gp.A0h = aWH; gp.A0l = aWL; gp.A1h = aCH; gp.A1l = aCL;
    gp.M = NP;
    ga.A0h = aAH; ga.A0l = aAL; ga.A2h = nullptr; ga.A2l = nullptr;
    ga.M = NA;

    const int yP = (NP + 127) / 128;   // 782
    const int yA = (NA + 127) / 128;   // 391
    dim3 gridPA(2, yP + yA);
    dim3 gridD(4, yA);

    // ---- Layer 1 (Kseg = 128): agg reads raw fp32 inputs ----
    jW.xf = x_author;
    jC.xf = x_paper;
    jA.xf = x_paper;
    k_agg3<128><<<2 * nbP + nbA, TPB>>>(jW, jC, jA, nbP, nbP, nbA);  // profiled (#4)
    gp.Ktot = 384; gp.Kseg = 128; gp.relu = 1;
    gp.A2h = xinPH; gp.A2l = xinPL;
    gp.Bh = BP1h; gp.Bl = BP1l; gp.bias = bc;
    gp.Ch = xpH[0]; gp.Cl = xpL[0]; gp.Cx = xpF[0];
    ga.Ktot = 256; ga.Kseg = 128; ga.relu = 1;
    ga.A1h = xinAH; ga.A1l = xinAL;
    ga.Bh = BA1h; ga.Bl = BA1l; ga.bias = bl1 + 256;
    ga.Ch = xaH[0]; ga.Cl = xaL[0]; ga.Cx = xaF[0];
    k_mgemm2<<<gridPA, TPB, SMEM_TOTAL>>>(gp, ga, yP);

    // ---- Layers 2..4 (Kseg = 256) ----
    int cur = 0;
    for (int l = 0; l < 3; l++) {
        jW.xf = xaF[cur];
        jC.xf = xpF[cur];
        jA.xf = xpF[cur];
        k_agg3<256><<<2 * nbP + nbA, TPB>>>(jW, jC, jA, nbP, nbP, nbA);
        int relu = (l < 2) ? 1 : 0;
        int needF = (l < 2) ? 1 : 0;   // layer-4 output feeds decoder only
        gp.Ktot = 768; gp.Kseg = 256; gp.relu = relu;
        gp.A2h = xpH[cur]; gp.A2l = xpL[cur];
        gp.Bh = BPh3 + (size_t)l * 256 * 768;
        gp.Bl = BPl3 + (size_t)l * 256 * 768;
        gp.bias = bc + (l + 1) * 256;
        gp.Ch = xpH[1 - cur]; gp.Cl = xpL[1 - cur];
        gp.Cx = needF ? xpF[1 - cur] : nullptr;
        ga.Ktot = 512; ga.Kseg = 256; ga.relu = relu;
        ga.A1h = xaH[cur]; ga.A1l = xaL[cur];
        ga.Bh = BAh3 + (size_t)l * 256 * 512;
        ga.Bl = BAl3 + (size_t)l * 256 * 512;
        ga.bias = bl + l * 768 + 256;
        ga.Ch = xaH[1 - cur]; ga.Cl = xaL[1 - cur];
        ga.Cx = needF ? xaF[1 - cur] : nullptr;
        k_mgemm2<<<gridPA, TPB, SMEM_TOTAL>>>(gp, ga, yP);
        cur ^= 1;
    }

    // ---- Decoder ----
    GemmP gd;
    gd.M = NA; gd.Ktot = 256; gd.Kseg = 256; gd.Nall = 512; gd.relu = 0;
    gd.A0h = xaH[cur]; gd.A0l = xaL[cur];
    gd.A1h = nullptr; gd.A1l = nullptr; gd.A2h = nullptr; gd.A2l = nullptr;
    gd.Bh = BDh; gd.Bl = BDl; gd.bias = nullptr;
    gd.Cf = TB; gd.Ch = nullptr; gd.Cl = nullptr; gd.Cx = nullptr;
    k_mgemm2<<<gridD, TPB, SMEM_TOTAL>>>(gd, gd, yA + 1);
    k_edge<<<(NEL * 32 + TPB - 1) / TPB, TPB>>>(esrc, edst, TB, dec_b1, dec_W2,
                                                dec_b2, out);
}